// round 8
// baseline (speedup 1.0000x reference)
#include <cuda_runtime.h>

// ElementwiseTensorProd_o0: per token t (262144 tokens), rank R=128:
//   out[t, 0:128]   = z0l[t, :] * z0r[t, :]
//   out[t, 128:256] = sum_{m=0..2} z1l[t, m, :] * z1r[t, m, :]
//
// Zero-reuse HBM stream at the traffic minimum (1.342 GB, ~90% of spec BW
// achieved). R4: best measured operating point = 1 float4-slot per thread
// (regs~38, occ~60%, DRAM 90.6%), streaming stores only (__stcs), plain
// cached loads, 512-thread blocks.

#define TOKENS 262144
#define RANK 128
#define V4_PER_ROW (RANK / 4)            // 32 float4 per 128-float row
#define THREADS_PER_BLOCK 512

__global__ void __launch_bounds__(THREADS_PER_BLOCK)
etp_o0_kernel(const float4* __restrict__ z0l,
              const float4* __restrict__ z1l,
              const float4* __restrict__ z0r,
              const float4* __restrict__ z1r,
              float4* __restrict__ out)
{
    // Global thread id over TOKENS * 32 float4-slots; exact grid coverage.
    const unsigned int i = blockIdx.x * THREADS_PER_BLOCK + threadIdx.x;

    const unsigned int c4 = i & (V4_PER_ROW - 1);   // 0..31 within rank
    const unsigned int t  = i >> 5;                 // token id

    // ---- path (0,0,0): scalar * scalar ----
    const unsigned int i0 = t * V4_PER_ROW + c4;
    float4 a0 = z0l[i0];
    float4 b0 = z0r[i0];

    // ---- path (1,1,0): contract irrep dim m=0..2 ----
    // z1 layout: (TOKENS, 3, RANK) -> t*96 + m*32 + c4 in float4 units.
    const unsigned int i1 = t * (3 * V4_PER_ROW) + c4;
    float4 a1 = z1l[i1];
    float4 b1 = z1r[i1];
    float4 a2 = z1l[i1 + V4_PER_ROW];
    float4 b2 = z1r[i1 + V4_PER_ROW];
    float4 a3 = z1l[i1 + 2 * V4_PER_ROW];
    float4 b3 = z1r[i1 + 2 * V4_PER_ROW];

    float4 o00;
    o00.x = a0.x * b0.x;
    o00.y = a0.y * b0.y;
    o00.z = a0.z * b0.z;
    o00.w = a0.w * b0.w;

    float4 o11;
    o11.x = fmaf(a1.x, b1.x, fmaf(a2.x, b2.x, a3.x * b3.x));
    o11.y = fmaf(a1.y, b1.y, fmaf(a2.y, b2.y, a3.y * b3.y));
    o11.z = fmaf(a1.z, b1.z, fmaf(a2.z, b2.z, a3.z * b3.z));
    o11.w = fmaf(a1.w, b1.w, fmaf(a2.w, b2.w, a3.w * b3.w));

    // Output layout: (TOKENS, 2*RANK) -> 64 float4 per token.
    const unsigned int o = t * (2 * V4_PER_ROW) + c4;
    __stcs(out + o, o00);
    __stcs(out + o + V4_PER_ROW, o11);
}

extern "C" void kernel_launch(void* const* d_in, const int* in_sizes, int n_in,
                              void* d_out, int out_size)
{
    (void)in_sizes; (void)n_in; (void)out_size;
    const float4* z0l = (const float4*)d_in[0];
    const float4* z1l = (const float4*)d_in[1];
    const float4* z0r = (const float4*)d_in[2];
    const float4* z1r = (const float4*)d_in[3];
    float4* out = (float4*)d_out;

    const unsigned int total_threads = TOKENS * V4_PER_ROW;        // 8,388,608
    const unsigned int blocks = total_threads / THREADS_PER_BLOCK; // 16384

    etp_o0_kernel<<<blocks, THREADS_PER_BLOCK>>>(z0l, z1l, z0r, z1r, out);
}